// round 1
// baseline (speedup 1.0000x reference)
#include <cuda_runtime.h>

#define BB   8
#define LL   384
#define HH   512
#define NHH  8
#define DHH  64
#define MS   384
#define RROWS 769          // rel index t = j - i + 384 in [1,767]; compute all 769 rows

// ---------------- scratch (device globals; no allocation allowed) ----------------
__device__ float g_q  [BB*LL*HH];
__device__ float g_k  [BB*LL*HH];
__device__ float g_v  [BB*LL*HH];
__device__ float g_vT [BB*NHH*DHH*LL];
__device__ float g_ctx[BB*LL*HH];
__device__ float g_R  [RROWS*HH];
__device__ float g_S  [BB*NHH*LL*LL];        // scores -> attn (in place)
__device__ float g_qR [BB*NHH*LL*RROWS];
__device__ float g_C  [BB*NHH*LL];
__device__ float g_D  [NHH*RROWS];

// ---------------- generic batched GEMM: C = A[M,K] * B[N,K]^T (+bias) ----------------
// batch z decomposed as (z/bdiv, z%bdiv) with independent outer/inner strides,
// which covers single GEMMs, per-(b,h) batched GEMMs, and strided outputs.
__global__ void gemm_nt(const float* __restrict__ A, const float* __restrict__ Bm,
                        const float* __restrict__ bias, float* __restrict__ C,
                        int M, int N, int K, int lda, int ldb, int ldc,
                        long long Ao, long long Ai, long long Bo, long long Bi,
                        long long Co, long long Ci, int bdiv)
{
    int z = blockIdx.z;
    A  += (long long)(z / bdiv) * Ao + (long long)(z % bdiv) * Ai;
    Bm += (long long)(z / bdiv) * Bo + (long long)(z % bdiv) * Bi;
    C  += (long long)(z / bdiv) * Co + (long long)(z % bdiv) * Ci;

    __shared__ float As[16][65];
    __shared__ float Bs[16][65];

    int tid = threadIdx.x;
    int tx = tid & 15, ty = tid >> 4;
    int bm = blockIdx.y * 64, bn = blockIdx.x * 64;

    float acc[4][4] = {};

    int ktiles = (K + 15) >> 4;
    for (int t = 0; t < ktiles; ++t) {
        int kb = t << 4;
#pragma unroll
        for (int l = 0; l < 4; ++l) {
            int idx = tid + l * 256;          // 1024 elems = 64 rows x 16 k
            int r  = idx >> 4;
            int kk = idx & 15;
            int gk = kb + kk;
            int gm = bm + r;
            As[kk][r] = (gm < M && gk < K) ? A[(long long)gm * lda + gk] : 0.f;
            int gn = bn + r;
            Bs[kk][r] = (gn < N && gk < K) ? Bm[(long long)gn * ldb + gk] : 0.f;
        }
        __syncthreads();
#pragma unroll
        for (int kk = 0; kk < 16; ++kk) {
            float a[4], b[4];
#pragma unroll
            for (int i = 0; i < 4; ++i) a[i] = As[kk][ty * 4 + i];
#pragma unroll
            for (int j = 0; j < 4; ++j) b[j] = Bs[kk][tx * 4 + j];
#pragma unroll
            for (int i = 0; i < 4; ++i)
#pragma unroll
                for (int j = 0; j < 4; ++j)
                    acc[i][j] += a[i] * b[j];
        }
        __syncthreads();
    }
#pragma unroll
    for (int i = 0; i < 4; ++i) {
        int gm = bm + ty * 4 + i;
        if (gm >= M) continue;
#pragma unroll
        for (int j = 0; j < 4; ++j) {
            int gn = bn + tx * 4 + j;
            if (gn < N) {
                float v = acc[i][j];
                if (bias) v += bias[gn];
                C[(long long)gm * ldc + gn] = v;
            }
        }
    }
}

// ---------------- small dot kernels: C[b,h,j] = u_h . k[b,j,h]; D[h,t] = v_h . R[t,h] ----
__global__ void dots_kernel(const float* __restrict__ u_bias, const float* __restrict__ v_bias)
{
    int idx = blockIdx.x * blockDim.x + threadIdx.x;
    const int NC = BB * NHH * LL;
    if (idx < NC) {
        int j = idx % LL;
        int h = (idx / LL) % NHH;
        int b = idx / (LL * NHH);
        const float* kp = g_k + ((long long)(b * LL + j) * NHH + h) * DHH;
        const float* up = u_bias + h * DHH;
        float s = 0.f;
#pragma unroll
        for (int d = 0; d < DHH; ++d) s += up[d] * kp[d];
        g_C[(b * NHH + h) * LL + j] = s;
    } else if (idx < NC + NHH * RROWS) {
        int id2 = idx - NC;
        int t = id2 % RROWS;
        int h = id2 / RROWS;
        const float* rp = g_R + (long long)t * HH + h * DHH;
        const float* vp = v_bias + h * DHH;
        float s = 0.f;
#pragma unroll
        for (int d = 0; d < DHH; ++d) s += vp[d] * rp[d];
        g_D[h * RROWS + t] = s;
    }
}

// ---------------- transpose v[b,j,h,d] -> vT[b,h,d,j] (so AV becomes an NT gemm) ------
__global__ void transpose_v()
{
    int idx = blockIdx.x * blockDim.x + threadIdx.x;
    if (idx >= BB * NHH * DHH * LL) return;
    int j = idx % LL;
    int d = (idx / LL) % DHH;
    int h = (idx / (LL * DHH)) % NHH;
    int b = idx / (LL * DHH * NHH);
    g_vT[idx] = g_v[((long long)(b * LL + j) * NHH + h) * DHH + d];
}

// ---------------- score assembly + mask + softmax (in-place into g_S) -----------------
// block = one (b,h,i) row, 128 threads * 3 columns each
__global__ void softmax_kernel(const int* __restrict__ seq_len)
{
    int bid = blockIdx.x;                 // (b*NH + h)*L + i
    int i = bid % LL;
    int h = (bid / LL) % NHH;
    int b = bid / (LL * NHH);
    int tid = threadIdx.x;

    float*       Srow  = g_S  + (long long)bid * LL;
    const float* qRrow = g_qR + (long long)bid * RROWS;
    const float* Crow  = g_C  + (b * NHH + h) * LL;
    const float* Drow  = g_D  + h * RROWS;
    int sl = seq_len[b];

    float s[3];
    float m = -1e30f;
#pragma unroll
    for (int r = 0; r < 3; ++r) {
        int j = tid + r * 128;
        int t = j - i + MS;
        float v = (Srow[j] + qRrow[t] + Crow[j] + Drow[t]) * 0.125f;  // 1/sqrt(64)
        if (j >= sl) v = -1e30f;
        s[r] = v;
        m = fmaxf(m, v);
    }
    __shared__ float redm[4];
#pragma unroll
    for (int off = 16; off > 0; off >>= 1) m = fmaxf(m, __shfl_xor_sync(0xffffffffu, m, off));
    if ((tid & 31) == 0) redm[tid >> 5] = m;
    __syncthreads();
    m = fmaxf(fmaxf(redm[0], redm[1]), fmaxf(redm[2], redm[3]));

    float sum = 0.f;
#pragma unroll
    for (int r = 0; r < 3; ++r) { s[r] = __expf(s[r] - m); sum += s[r]; }
#pragma unroll
    for (int off = 16; off > 0; off >>= 1) sum += __shfl_xor_sync(0xffffffffu, sum, off);
    __shared__ float reds[4];
    if ((tid & 31) == 0) reds[tid >> 5] = sum;
    __syncthreads();
    sum = reds[0] + reds[1] + reds[2] + reds[3];
    float inv = 1.f / sum;
#pragma unroll
    for (int r = 0; r < 3; ++r) Srow[tid + r * 128] = s[r] * inv;
}

// ------------------------------------ launch ------------------------------------------
extern "C" void kernel_launch(void* const* d_in, const int* in_sizes, int n_in,
                              void* d_out, int out_size)
{
    const float* key    = (const float*)d_in[0];
    const float* query  = (const float*)d_in[1];
    const float* value  = (const float*)d_in[2];
    const int*   seqlen = (const int*)  d_in[3];
    const float* pe     = (const float*)d_in[4];
    const float* Wk = (const float*)d_in[5];  const float* bk = (const float*)d_in[6];
    const float* Wq = (const float*)d_in[7];  const float* bq = (const float*)d_in[8];
    const float* Wv = (const float*)d_in[9];  const float* bv = (const float*)d_in[10];
    const float* Wr = (const float*)d_in[11]; const float* br = (const float*)d_in[12];
    const float* u_bias = (const float*)d_in[13];
    const float* v_bias = (const float*)d_in[14];
    const float* Wff = (const float*)d_in[15]; const float* bff = (const float*)d_in[16];
    float* out = (float*)d_out;

    float *q_, *k_, *v_, *vT_, *ctx_, *R_, *S_, *qR_;
    cudaGetSymbolAddress((void**)&q_,   g_q);
    cudaGetSymbolAddress((void**)&k_,   g_k);
    cudaGetSymbolAddress((void**)&v_,   g_v);
    cudaGetSymbolAddress((void**)&vT_,  g_vT);
    cudaGetSymbolAddress((void**)&ctx_, g_ctx);
    cudaGetSymbolAddress((void**)&R_,   g_R);
    cudaGetSymbolAddress((void**)&S_,   g_S);
    cudaGetSymbolAddress((void**)&qR_,  g_qR);

    const int M  = BB * LL;      // 3072
    // ---- projections: x @ W.T + b ----
    dim3 gp((HH + 63) / 64, (M + 63) / 64, 1);
    gemm_nt<<<gp, 256>>>(query, Wq, bq, q_, M, HH, HH, HH, HH, HH, 0,0,0,0,0,0, 1);
    gemm_nt<<<gp, 256>>>(key,   Wk, bk, k_, M, HH, HH, HH, HH, HH, 0,0,0,0,0,0, 1);
    gemm_nt<<<gp, 256>>>(value, Wv, bv, v_, M, HH, HH, HH, HH, HH, 0,0,0,0,0,0, 1);
    dim3 gr((HH + 63) / 64, (RROWS + 63) / 64, 1);
    gemm_nt<<<gr, 256>>>(pe, Wr, br, R_, RROWS, HH, HH, HH, HH, HH, 0,0,0,0,0,0, 1);

    // ---- bias dots + v transpose ----
    int ndots = BB * NHH * LL + NHH * RROWS;
    dots_kernel<<<(ndots + 255) / 256, 256>>>(u_bias, v_bias);
    transpose_v<<<(BB * NHH * DHH * LL + 255) / 256, 256>>>();

    // ---- A term: S[b,h] = q_h @ k_h^T  (batch = B*NH = 64) ----
    dim3 gs((LL + 63) / 64, (LL + 63) / 64, BB * NHH);
    gemm_nt<<<gs, 256>>>(q_, k_, nullptr, S_, LL, LL, DHH, HH, HH, LL,
                         (long long)LL * HH, DHH,
                         (long long)LL * HH, DHH,
                         (long long)NHH * LL * LL, (long long)LL * LL, NHH);

    // ---- Bt term: qR[b,h] = q_h @ R_h^T  (N = 769) ----
    dim3 gq2((RROWS + 63) / 64, (LL + 63) / 64, BB * NHH);
    gemm_nt<<<gq2, 256>>>(q_, R_, nullptr, qR_, LL, RROWS, DHH, HH, HH, RROWS,
                          (long long)LL * HH, DHH,
                          0, DHH,
                          (long long)NHH * LL * RROWS, (long long)LL * RROWS, NHH);

    // ---- scores + mask + softmax ----
    softmax_kernel<<<BB * NHH * LL, 128>>>(seqlen);

    // ---- AV: ctx[b,i,h,:] = attn[b,h] @ v_h  (vT so it is NT) ----
    dim3 gav((DHH + 63) / 64, (LL + 63) / 64, BB * NHH);
    gemm_nt<<<gav, 256>>>(S_, vT_, nullptr, ctx_, LL, DHH, LL, LL, LL, HH,
                          (long long)NHH * LL * LL, (long long)LL * LL,
                          (long long)NHH * DHH * LL, (long long)DHH * LL,
                          (long long)LL * HH, DHH, NHH);

    // ---- final FF: out = ctx @ Wff.T + bff ----
    gemm_nt<<<gp, 256>>>(ctx_, Wff, bff, out, M, HH, HH, HH, HH, HH, 0,0,0,0,0,0, 1);
}

// round 2
// speedup vs baseline: 1.9556x; 1.9556x over previous
#include <cuda_runtime.h>

#define BB   8
#define LL   384
#define HH   512
#define NHH  8
#define DHH  64
#define MS   384
#define RROWS 769

// ---------------- scratch (device globals; no allocation allowed) ----------------
__device__ float g_q  [BB*LL*HH];
__device__ float g_k  [BB*LL*HH];
__device__ float g_v  [BB*LL*HH];
__device__ float g_vT [BB*NHH*DHH*LL];
__device__ float g_ctx[BB*LL*HH];
__device__ float g_R  [RROWS*HH];
__device__ float g_S  [BB*NHH*LL*LL];
__device__ float g_qR [BB*NHH*LL*RROWS];
__device__ float g_C  [BB*NHH*LL];
__device__ float g_D  [NHH*RROWS];

// ---------------- helpers ----------------
__device__ __forceinline__ float tf32r(float x) {
    unsigned u;
    asm("cvt.rna.tf32.f32 %0, %1;" : "=r"(u) : "f"(x));
    return __uint_as_float(u);
}

__device__ __forceinline__ void mma_tf32(float c[4],
                                         unsigned a0, unsigned a1, unsigned a2, unsigned a3,
                                         unsigned b0, unsigned b1)
{
    asm volatile(
        "mma.sync.aligned.m16n8k8.row.col.f32.tf32.tf32.f32 "
        "{%0,%1,%2,%3},{%4,%5,%6,%7},{%8,%9},{%0,%1,%2,%3};\n"
        : "+f"(c[0]), "+f"(c[1]), "+f"(c[2]), "+f"(c[3])
        : "r"(a0), "r"(a1), "r"(a2), "r"(a3), "r"(b0), "r"(b1));
}

// ---------------- tensor-core NT GEMM: C = A[M,K] * B[N,K]^T (+bias) ----------------
// 256 threads = 8 warps. Block tile BM x BN, warp tile WM x WN, k-tile 16.
// Batched via blockIdx.z with (outer, inner) stride decomposition like before.
template<int BM, int BN, int WM, int WN>
__global__ void __launch_bounds__(256, 2)
gemm_tc(const float* __restrict__ A, const float* __restrict__ Bm,
        const float* __restrict__ bias, float* __restrict__ C,
        int M, int N, int K, int lda, int ldb, int ldc,
        long long Ao, long long Ai, long long Bo, long long Bi,
        long long Co, long long Ci, int bdiv)
{
    constexpr int BK  = 16;
    constexpr int WGM = BM / WM;               // warp grid rows
    constexpr int MI  = WM / 16;
    constexpr int NI  = WN / 8;
    static_assert((BM / WM) * (BN / WN) == 8, "8 warps");

    int z = blockIdx.z;
    A  += (long long)(z / bdiv) * Ao + (long long)(z % bdiv) * Ai;
    Bm += (long long)(z / bdiv) * Bo + (long long)(z % bdiv) * Bi;
    C  += (long long)(z / bdiv) * Co + (long long)(z % bdiv) * Ci;

    __shared__ float As[2][BK][BM + 4];
    __shared__ float Bs[2][BK][BN + 4];

    int tid  = threadIdx.x;
    int lane = tid & 31;
    int wid  = tid >> 5;
    int wm   = (wid % WGM) * WM;
    int wn   = (wid / WGM) * WN;
    int bm   = blockIdx.y * BM;
    int bn   = blockIdx.x * BN;
    int r0   = lane >> 2;
    int c0   = lane & 3;

    float acc[MI][NI][4];
#pragma unroll
    for (int mi = 0; mi < MI; ++mi)
#pragma unroll
        for (int ni = 0; ni < NI; ++ni)
#pragma unroll
            for (int t = 0; t < 4; ++t) acc[mi][ni][t] = 0.f;

#define LOADTILE(T, BUF)                                                              \
    {                                                                                 \
        int kb = (T) * BK;                                                            \
        _Pragma("unroll")                                                             \
        for (int i = tid; i < BM * 4; i += 256) {                                     \
            int r = i >> 2, cc = (i & 3) << 2;                                        \
            int gm = bm + r;                                                          \
            float4 v = make_float4(0.f, 0.f, 0.f, 0.f);                               \
            if (gm < M) v = *(const float4*)(A + (long long)gm * lda + kb + cc);      \
            As[BUF][cc + 0][r] = tf32r(v.x);                                          \
            As[BUF][cc + 1][r] = tf32r(v.y);                                          \
            As[BUF][cc + 2][r] = tf32r(v.z);                                          \
            As[BUF][cc + 3][r] = tf32r(v.w);                                          \
        }                                                                             \
        _Pragma("unroll")                                                             \
        for (int i = tid; i < BN * 4; i += 256) {                                     \
            int r = i >> 2, cc = (i & 3) << 2;                                        \
            int gn = bn + r;                                                          \
            float4 v = make_float4(0.f, 0.f, 0.f, 0.f);                               \
            if (gn < N) v = *(const float4*)(Bm + (long long)gn * ldb + kb + cc);     \
            Bs[BUF][cc + 0][r] = tf32r(v.x);                                          \
            Bs[BUF][cc + 1][r] = tf32r(v.y);                                          \
            Bs[BUF][cc + 2][r] = tf32r(v.z);                                          \
            Bs[BUF][cc + 3][r] = tf32r(v.w);                                          \
        }                                                                             \
    }

    int nt = K / BK;
    LOADTILE(0, 0)
    __syncthreads();

    for (int t = 0; t < nt; ++t) {
        int buf = t & 1;
        if (t + 1 < nt) LOADTILE(t + 1, buf ^ 1)

#pragma unroll
        for (int kk = 0; kk < BK; kk += 8) {
            unsigned a[MI][4], b[NI][2];
#pragma unroll
            for (int mi = 0; mi < MI; ++mi) {
                int m0 = wm + mi * 16 + r0;
                a[mi][0] = __float_as_uint(As[buf][kk + c0    ][m0    ]);
                a[mi][1] = __float_as_uint(As[buf][kk + c0    ][m0 + 8]);
                a[mi][2] = __float_as_uint(As[buf][kk + c0 + 4][m0    ]);
                a[mi][3] = __float_as_uint(As[buf][kk + c0 + 4][m0 + 8]);
            }
#pragma unroll
            for (int ni = 0; ni < NI; ++ni) {
                int n0 = wn + ni * 8 + r0;
                b[ni][0] = __float_as_uint(Bs[buf][kk + c0    ][n0]);
                b[ni][1] = __float_as_uint(Bs[buf][kk + c0 + 4][n0]);
            }
#pragma unroll
            for (int mi = 0; mi < MI; ++mi)
#pragma unroll
                for (int ni = 0; ni < NI; ++ni)
                    mma_tf32(acc[mi][ni], a[mi][0], a[mi][1], a[mi][2], a[mi][3],
                             b[ni][0], b[ni][1]);
        }
        __syncthreads();
    }

    // epilogue
#pragma unroll
    for (int mi = 0; mi < MI; ++mi) {
        int rA = bm + wm + mi * 16 + r0;
#pragma unroll
        for (int ni = 0; ni < NI; ++ni) {
            int cA = bn + wn + ni * 8 + c0 * 2;
            float b0 = 0.f, b1 = 0.f;
            if (bias) {
                if (cA < N)     b0 = bias[cA];
                if (cA + 1 < N) b1 = bias[cA + 1];
            }
            if (rA < M) {
                if (cA < N)     C[(long long)rA * ldc + cA]     = acc[mi][ni][0] + b0;
                if (cA + 1 < N) C[(long long)rA * ldc + cA + 1] = acc[mi][ni][1] + b1;
            }
            int rB = rA + 8;
            if (rB < M) {
                if (cA < N)     C[(long long)rB * ldc + cA]     = acc[mi][ni][2] + b0;
                if (cA + 1 < N) C[(long long)rB * ldc + cA + 1] = acc[mi][ni][3] + b1;
            }
        }
    }
#undef LOADTILE
}

// ---------------- small dot kernels ----------------
__global__ void dots_kernel(const float* __restrict__ u_bias, const float* __restrict__ v_bias)
{
    int idx = blockIdx.x * blockDim.x + threadIdx.x;
    const int NC = BB * NHH * LL;
    if (idx < NC) {
        int j = idx % LL;
        int h = (idx / LL) % NHH;
        int b = idx / (LL * NHH);
        const float* kp = g_k + ((long long)(b * LL + j) * NHH + h) * DHH;
        const float* up = u_bias + h * DHH;
        float s = 0.f;
#pragma unroll
        for (int d = 0; d < DHH; ++d) s += up[d] * kp[d];
        g_C[(b * NHH + h) * LL + j] = s;
    } else if (idx < NC + NHH * RROWS) {
        int id2 = idx - NC;
        int t = id2 % RROWS;
        int h = id2 / RROWS;
        const float* rp = g_R + (long long)t * HH + h * DHH;
        const float* vp = v_bias + h * DHH;
        float s = 0.f;
#pragma unroll
        for (int d = 0; d < DHH; ++d) s += vp[d] * rp[d];
        g_D[h * RROWS + t] = s;
    }
}

// ---------------- transpose v[b,j,h,d] -> vT[b,h,d,j] ----------------
__global__ void transpose_v()
{
    int idx = blockIdx.x * blockDim.x + threadIdx.x;
    if (idx >= BB * NHH * DHH * LL) return;
    int j = idx % LL;
    int d = (idx / LL) % DHH;
    int h = (idx / (LL * DHH)) % NHH;
    int b = idx / (LL * DHH * NHH);
    g_vT[idx] = g_v[((long long)(b * LL + j) * NHH + h) * DHH + d];
}

// ---------------- score assembly + mask + softmax (in-place in g_S) ----------------
__global__ void softmax_kernel(const int* __restrict__ seq_len)
{
    int bid = blockIdx.x;                 // (b*NH + h)*L + i
    int i = bid % LL;
    int h = (bid / LL) % NHH;
    int b = bid / (LL * NHH);
    int tid = threadIdx.x;

    float*       Srow  = g_S  + (long long)bid * LL;
    const float* qRrow = g_qR + (long long)bid * RROWS;
    const float* Crow  = g_C  + (b * NHH + h) * LL;
    const float* Drow  = g_D  + h * RROWS;
    int sl = seq_len[b];

    float s[3];
    float m = -1e30f;
#pragma unroll
    for (int r = 0; r < 3; ++r) {
        int j = tid + r * 128;
        int t = j - i + MS;
        float v = (Srow[j] + qRrow[t] + Crow[j] + Drow[t]) * 0.125f;
        if (j >= sl) v = -1e30f;
        s[r] = v;
        m = fmaxf(m, v);
    }
    __shared__ float redm[4];
#pragma unroll
    for (int off = 16; off > 0; off >>= 1) m = fmaxf(m, __shfl_xor_sync(0xffffffffu, m, off));
    if ((tid & 31) == 0) redm[tid >> 5] = m;
    __syncthreads();
    m = fmaxf(fmaxf(redm[0], redm[1]), fmaxf(redm[2], redm[3]));

    float sum = 0.f;
#pragma unroll
    for (int r = 0; r < 3; ++r) { s[r] = __expf(s[r] - m); sum += s[r]; }
#pragma unroll
    for (int off = 16; off > 0; off >>= 1) sum += __shfl_xor_sync(0xffffffffu, sum, off);
    __shared__ float reds[4];
    if ((tid & 31) == 0) reds[tid >> 5] = sum;
    __syncthreads();
    sum = reds[0] + reds[1] + reds[2] + reds[3];
    float inv = 1.f / sum;
#pragma unroll
    for (int r = 0; r < 3; ++r) Srow[tid + r * 128] = s[r] * inv;
}

// ------------------------------------ launch ------------------------------------------
extern "C" void kernel_launch(void* const* d_in, const int* in_sizes, int n_in,
                              void* d_out, int out_size)
{
    const float* key    = (const float*)d_in[0];
    const float* query  = (const float*)d_in[1];
    const float* value  = (const float*)d_in[2];
    const int*   seqlen = (const int*)  d_in[3];
    const float* pe     = (const float*)d_in[4];
    const float* Wk = (const float*)d_in[5];  const float* bk = (const float*)d_in[6];
    const float* Wq = (const float*)d_in[7];  const float* bq = (const float*)d_in[8];
    const float* Wv = (const float*)d_in[9];  const float* bv = (const float*)d_in[10];
    const float* Wr = (const float*)d_in[11]; const float* br = (const float*)d_in[12];
    const float* u_bias = (const float*)d_in[13];
    const float* v_bias = (const float*)d_in[14];
    const float* Wff = (const float*)d_in[15]; const float* bff = (const float*)d_in[16];
    float* out = (float*)d_out;

    float *q_, *k_, *v_, *vT_, *ctx_, *R_, *S_, *qR_;
    cudaGetSymbolAddress((void**)&q_,   g_q);
    cudaGetSymbolAddress((void**)&k_,   g_k);
    cudaGetSymbolAddress((void**)&v_,   g_v);
    cudaGetSymbolAddress((void**)&vT_,  g_vT);
    cudaGetSymbolAddress((void**)&ctx_, g_ctx);
    cudaGetSymbolAddress((void**)&R_,   g_R);
    cudaGetSymbolAddress((void**)&S_,   g_S);
    cudaGetSymbolAddress((void**)&qR_,  g_qR);

    const int M = BB * LL;   // 3072

    // ---- projections: x @ W.T + b    (BM=64 -> 192 blocks, fills the chip) ----
    dim3 gp(HH / 128, M / 64, 1);                       // (4, 48)
    gemm_tc<64,128,32,32><<<gp, 256>>>(query, Wq, bq, q_, M, HH, HH, HH, HH, HH,
                                       0,0,0,0,0,0, 1);
    gemm_tc<64,128,32,32><<<gp, 256>>>(key,   Wk, bk, k_, M, HH, HH, HH, HH, HH,
                                       0,0,0,0,0,0, 1);
    gemm_tc<64,128,32,32><<<gp, 256>>>(value, Wv, bv, v_, M, HH, HH, HH, HH, HH,
                                       0,0,0,0,0,0, 1);
    dim3 gr(HH / 128, (RROWS + 63) / 64, 1);            // (4, 13)
    gemm_tc<64,128,32,32><<<gr, 256>>>(pe, Wr, br, R_, RROWS, HH, HH, HH, HH, HH,
                                       0,0,0,0,0,0, 1);

    // ---- bias dots + v transpose ----
    int ndots = BB * NHH * LL + NHH * RROWS;
    dots_kernel<<<(ndots + 255) / 256, 256>>>(u_bias, v_bias);
    transpose_v<<<(BB * NHH * DHH * LL + 255) / 256, 256>>>();

    // ---- A term: S[b,h] = q_h @ k_h^T  (batch = 64) ----
    dim3 gs(LL / 128, LL / 128, BB * NHH);              // (3, 3, 64)
    gemm_tc<128,128,64,32><<<gs, 256>>>(q_, k_, nullptr, S_, LL, LL, DHH, HH, HH, LL,
                                        (long long)LL * HH, DHH,
                                        (long long)LL * HH, DHH,
                                        (long long)NHH * LL * LL, (long long)LL * LL, NHH);

    // ---- Bt term: qR[b,h] = q_h @ R_h^T  (N = 769) ----
    dim3 gq2((RROWS + 127) / 128, LL / 128, BB * NHH);  // (7, 3, 64)
    gemm_tc<128,128,64,32><<<gq2, 256>>>(q_, R_, nullptr, qR_, LL, RROWS, DHH, HH, HH, RROWS,
                                         (long long)LL * HH, DHH,
                                         0, DHH,
                                         (long long)NHH * LL * RROWS, (long long)LL * RROWS, NHH);

    // ---- scores + mask + softmax ----
    softmax_kernel<<<BB * NHH * LL, 128>>>(seqlen);

    // ---- AV: ctx[b,i,h,:] = attn[b,h] @ v_h ----
    dim3 gav(1, LL / 128, BB * NHH);                    // (1, 3, 64)
    gemm_tc<128,64,64,16><<<gav, 256>>>(S_, vT_, nullptr, ctx_, LL, DHH, LL, LL, LL, HH,
                                        (long long)NHH * LL * LL, (long long)LL * LL,
                                        (long long)NHH * DHH * LL, (long long)DHH * LL,
                                        (long long)LL * HH, DHH, NHH);

    // ---- final FF: out = ctx @ Wff.T + bff ----
    gemm_tc<64,128,32,32><<<gp, 256>>>(ctx_, Wff, bff, out, M, HH, HH, HH, HH, HH,
                                       0,0,0,0,0,0, 1);
}

// round 3
// speedup vs baseline: 3.4239x; 1.7508x over previous
#include <cuda_runtime.h>

#define BB   8
#define LL   384
#define HH   512
#define NHH  8
#define DHH  64
#define MS   384
#define RROWS 769

// ---------------- scratch (device globals; no allocation allowed) ----------------
__device__ float g_q  [BB*LL*HH];
__device__ float g_k  [BB*LL*HH];
__device__ float g_v  [BB*LL*HH];
__device__ float g_vT [BB*NHH*DHH*LL];
__device__ float g_ctx[BB*LL*HH];
__device__ float g_R  [RROWS*HH];
__device__ float g_S  [BB*NHH*LL*LL];
__device__ float g_qR [BB*NHH*LL*RROWS];
__device__ float g_C  [BB*NHH*LL];
__device__ float g_D  [NHH*RROWS];

// ---------------- helpers ----------------
__device__ __forceinline__ float tf32r(float x) {
    unsigned u;
    asm("cvt.rna.tf32.f32 %0, %1;" : "=r"(u) : "f"(x));
    return __uint_as_float(u);
}
__device__ __forceinline__ unsigned frg(float x) {
    unsigned u;
    asm("cvt.rna.tf32.f32 %0, %1;" : "=r"(u) : "f"(x));
    return u;
}

__device__ __forceinline__ void mma_tf32(float c[4],
                                         unsigned a0, unsigned a1, unsigned a2, unsigned a3,
                                         unsigned b0, unsigned b1)
{
    asm volatile(
        "mma.sync.aligned.m16n8k8.row.col.f32.tf32.tf32.f32 "
        "{%0,%1,%2,%3},{%4,%5,%6,%7},{%8,%9},{%0,%1,%2,%3};\n"
        : "+f"(c[0]), "+f"(c[1]), "+f"(c[2]), "+f"(c[3])
        : "r"(a0), "r"(a1), "r"(a2), "r"(a3), "r"(b0), "r"(b1));
}

__device__ __forceinline__ void cp16(unsigned dst, const void* src, bool pred) {
    int sz = pred ? 16 : 0;
    asm volatile("cp.async.cg.shared.global [%0], [%1], 16, %2;\n"
                 :: "r"(dst), "l"(src), "r"(sz));
}

// ---------------- descriptor pack: several NT GEMMs in one launch ----------------
struct GDesc {
    const float* A; const float* B; const float* bias; float* C;
    int M, N, K, lda, ldb, ldc;
    long long Ao, Ai, Bo, Bi, Co, Ci;
    int bdiv;
    int zcount;
};
struct GPack { GDesc d[4]; };

static GDesc mkdesc(const float* A, const float* B, const float* bias, float* C,
                    int M, int N, int K, int lda, int ldb, int ldc,
                    long long Ao, long long Ai, long long Bo, long long Bi,
                    long long Co, long long Ci, int bdiv, int zcount)
{
    GDesc d; d.A=A; d.B=B; d.bias=bias; d.C=C; d.M=M; d.N=N; d.K=K;
    d.lda=lda; d.ldb=ldb; d.ldc=ldc; d.Ao=Ao; d.Ai=Ai; d.Bo=Bo; d.Bi=Bi;
    d.Co=Co; d.Ci=Ci; d.bdiv=bdiv; d.zcount=zcount; return d;
}

// ---------------- tf32 tensor-core NT GEMM with cp.async double buffer ----------------
// C = A[M,K] * B[N,K]^T (+bias). 256 threads = 8 warps. BK=32 fixed.
template<int BM, int BN, int WM, int WN>
__global__ void __launch_bounds__(256)
gemm_tc(GPack P)
{
    constexpr int BK    = 32;
    constexpr int LDS_S = BK + 4;                 // 36 floats: conflict-free pad
    constexpr int WGM   = BM / WM;
    constexpr int MI    = WM / 16;
    constexpr int NI    = WN / 8;
    constexpr int ACH   = BM * (BK / 4) / 256;    // float4 chunks per thread (A)
    constexpr int BCH   = BN * (BK / 4) / 256;    // (B)
    static_assert(WGM * (BN / WN) == 8, "8 warps");

    extern __shared__ float sm[];
    float* Asm = sm;                              // [2][BM][LDS_S]
    float* Bsm = sm + 2 * BM * LDS_S;             // [2][BN][LDS_S]
    unsigned sb = (unsigned)__cvta_generic_to_shared(sm);
    unsigned sbB = sb + 2u * BM * LDS_S * 4u;

    int zz = blockIdx.z;
    int di = 0;
    while (zz >= P.d[di].zcount) { zz -= P.d[di].zcount; ++di; }
    GDesc D = P.d[di];

    int bm = blockIdx.y * BM;
    int bn = blockIdx.x * BN;
    if (bm >= D.M || bn >= D.N) return;

    const float* A = D.A + (long long)(zz / D.bdiv) * D.Ao + (long long)(zz % D.bdiv) * D.Ai;
    const float* B = D.B + (long long)(zz / D.bdiv) * D.Bo + (long long)(zz % D.bdiv) * D.Bi;
    float*       C = D.C + (long long)(zz / D.bdiv) * D.Co + (long long)(zz % D.bdiv) * D.Ci;

    int tid  = threadIdx.x;
    int lane = tid & 31;
    int wid  = tid >> 5;
    int wm   = (wid % WGM) * WM;
    int wn   = (wid / WGM) * WN;
    int r0   = lane >> 2;
    int c0   = lane & 3;

    float acc[MI][NI][4];
#pragma unroll
    for (int mi = 0; mi < MI; ++mi)
#pragma unroll
        for (int ni = 0; ni < NI; ++ni)
#pragma unroll
            for (int t = 0; t < 4; ++t) acc[mi][ni][t] = 0.f;

#define LOADSTAGE(T, BUF)                                                             \
    {                                                                                 \
        int kb = (T) * BK;                                                            \
        _Pragma("unroll")                                                             \
        for (int i = 0; i < ACH; ++i) {                                               \
            int e = tid + i * 256;                                                    \
            int row = e >> 3, kc = (e & 7) << 2;                                      \
            bool p = (bm + row) < D.M;                                                \
            const float* src = A + (long long)(bm + row) * D.lda + kb + kc;           \
            unsigned dst = sb + (((BUF) * BM + row) * LDS_S + kc) * 4u;               \
            cp16(dst, src, p);                                                        \
        }                                                                             \
        _Pragma("unroll")                                                             \
        for (int i = 0; i < BCH; ++i) {                                               \
            int e = tid + i * 256;                                                    \
            int row = e >> 3, kc = (e & 7) << 2;                                      \
            bool p = (bn + row) < D.N;                                                \
            const float* src = B + (long long)(bn + row) * D.ldb + kb + kc;           \
            unsigned dst = sbB + (((BUF) * BN + row) * LDS_S + kc) * 4u;              \
            cp16(dst, src, p);                                                        \
        }                                                                             \
        asm volatile("cp.async.commit_group;\n");                                     \
    }

#define MATH(BUF)                                                                     \
    _Pragma("unroll")                                                                 \
    for (int kk = 0; kk < BK; kk += 8) {                                              \
        unsigned a[MI][4], b[NI][2];                                                  \
        _Pragma("unroll")                                                             \
        for (int mi = 0; mi < MI; ++mi) {                                             \
            int m0 = wm + mi * 16 + r0;                                               \
            const float* ap0 = Asm + ((BUF) * BM + m0) * LDS_S + kk + c0;             \
            const float* ap1 = Asm + ((BUF) * BM + m0 + 8) * LDS_S + kk + c0;         \
            a[mi][0] = frg(ap0[0]);                                                   \
            a[mi][1] = frg(ap1[0]);                                                   \
            a[mi][2] = frg(ap0[4]);                                                   \
            a[mi][3] = frg(ap1[4]);                                                   \
        }                                                                             \
        _Pragma("unroll")                                                             \
        for (int ni = 0; ni < NI; ++ni) {                                             \
            int n0 = wn + ni * 8 + r0;                                                \
            const float* bp = Bsm + ((BUF) * BN + n0) * LDS_S + kk + c0;              \
            b[ni][0] = frg(bp[0]);                                                    \
            b[ni][1] = frg(bp[4]);                                                    \
        }                                                                             \
        _Pragma("unroll")                                                             \
        for (int mi = 0; mi < MI; ++mi)                                               \
            _Pragma("unroll")                                                         \
            for (int ni = 0; ni < NI; ++ni)                                           \
                mma_tf32(acc[mi][ni], a[mi][0], a[mi][1], a[mi][2], a[mi][3],         \
                         b[ni][0], b[ni][1]);                                         \
    }

    int nt = D.K / BK;
    LOADSTAGE(0, 0)

    for (int t = 0; t < nt; ++t) {
        int buf = t & 1;
        if (t + 1 < nt) {
            LOADSTAGE(t + 1, buf ^ 1)
            asm volatile("cp.async.wait_group 1;\n");
        } else {
            asm volatile("cp.async.wait_group 0;\n");
        }
        __syncthreads();
        MATH(buf)
        __syncthreads();
    }

    // epilogue
#pragma unroll
    for (int mi = 0; mi < MI; ++mi) {
        int rA = bm + wm + mi * 16 + r0;
#pragma unroll
        for (int ni = 0; ni < NI; ++ni) {
            int cA = bn + wn + ni * 8 + c0 * 2;
            float b0 = 0.f, b1 = 0.f;
            if (D.bias) {
                if (cA < D.N)     b0 = D.bias[cA];
                if (cA + 1 < D.N) b1 = D.bias[cA + 1];
            }
            if (rA < D.M) {
                if (cA < D.N)     C[(long long)rA * D.ldc + cA]     = acc[mi][ni][0] + b0;
                if (cA + 1 < D.N) C[(long long)rA * D.ldc + cA + 1] = acc[mi][ni][1] + b1;
            }
            int rB = rA + 8;
            if (rB < D.M) {
                if (cA < D.N)     C[(long long)rB * D.ldc + cA]     = acc[mi][ni][2] + b0;
                if (cA + 1 < D.N) C[(long long)rB * D.ldc + cA + 1] = acc[mi][ni][3] + b1;
            }
        }
    }
#undef LOADSTAGE
#undef MATH
}

// ---------------- small dot kernels ----------------
__global__ void dots_kernel(const float* __restrict__ u_bias, const float* __restrict__ v_bias)
{
    int idx = blockIdx.x * blockDim.x + threadIdx.x;
    const int NC = BB * NHH * LL;
    if (idx < NC) {
        int j = idx % LL;
        int h = (idx / LL) % NHH;
        int b = idx / (LL * NHH);
        const float* kp = g_k + ((long long)(b * LL + j) * NHH + h) * DHH;
        const float* up = u_bias + h * DHH;
        float s = 0.f;
#pragma unroll
        for (int d = 0; d < DHH; ++d) s += up[d] * kp[d];
        g_C[(b * NHH + h) * LL + j] = s;
    } else if (idx < NC + NHH * RROWS) {
        int id2 = idx - NC;
        int t = id2 % RROWS;
        int h = id2 / RROWS;
        const float* rp = g_R + (long long)t * HH + h * DHH;
        const float* vp = v_bias + h * DHH;
        float s = 0.f;
#pragma unroll
        for (int d = 0; d < DHH; ++d) s += vp[d] * rp[d];
        g_D[h * RROWS + t] = s;
    }
}

// ---------------- transpose v[b,j,h,d] -> vT[b,h,d,j] ----------------
__global__ void transpose_v()
{
    int idx = blockIdx.x * blockDim.x + threadIdx.x;
    if (idx >= BB * NHH * DHH * LL) return;
    int j = idx % LL;
    int d = (idx / LL) % DHH;
    int h = (idx / (LL * DHH)) % NHH;
    int b = idx / (LL * DHH * NHH);
    g_vT[idx] = g_v[((long long)(b * LL + j) * NHH + h) * DHH + d];
}

// ---------------- score assembly + mask + softmax (in-place in g_S) ----------------
__global__ void softmax_kernel(const int* __restrict__ seq_len)
{
    int bid = blockIdx.x;                 // (b*NH + h)*L + i
    int i = bid % LL;
    int h = (bid / LL) % NHH;
    int b = bid / (LL * NHH);
    int tid = threadIdx.x;

    float*       Srow  = g_S  + (long long)bid * LL;
    const float* qRrow = g_qR + (long long)bid * RROWS;
    const float* Crow  = g_C  + (b * NHH + h) * LL;
    const float* Drow  = g_D  + h * RROWS;
    int sl = seq_len[b];

    float s[3];
    float m = -1e30f;
#pragma unroll
    for (int r = 0; r < 3; ++r) {
        int j = tid + r * 128;
        int t = j - i + MS;
        float v = (Srow[j] + qRrow[t] + Crow[j] + Drow[t]) * 0.125f;
        if (j >= sl) v = -1e30f;
        s[r] = v;
        m = fmaxf(m, v);
    }
    __shared__ float redm[4];
#pragma unroll
    for (int off = 16; off > 0; off >>= 1) m = fmaxf(m, __shfl_xor_sync(0xffffffffu, m, off));
    if ((tid & 31) == 0) redm[tid >> 5] = m;
    __syncthreads();
    m = fmaxf(fmaxf(redm[0], redm[1]), fmaxf(redm[2], redm[3]));

    float sum = 0.f;
#pragma unroll
    for (int r = 0; r < 3; ++r) { s[r] = __expf(s[r] - m); sum += s[r]; }
#pragma unroll
    for (int off = 16; off > 0; off >>= 1) sum += __shfl_xor_sync(0xffffffffu, sum, off);
    __shared__ float reds[4];
    if ((tid & 31) == 0) reds[tid >> 5] = sum;
    __syncthreads();
    sum = reds[0] + reds[1] + reds[2] + reds[3];
    float inv = 1.f / sum;
#pragma unroll
    for (int r = 0; r < 3; ++r) Srow[tid + r * 128] = s[r] * inv;
}

// ------------------------------------ launch ------------------------------------------
extern "C" void kernel_launch(void* const* d_in, const int* in_sizes, int n_in,
                              void* d_out, int out_size)
{
    const float* key    = (const float*)d_in[0];
    const float* query  = (const float*)d_in[1];
    const float* value  = (const float*)d_in[2];
    const int*   seqlen = (const int*)  d_in[3];
    const float* pe     = (const float*)d_in[4];
    const float* Wk = (const float*)d_in[5];  const float* bk = (const float*)d_in[6];
    const float* Wq = (const float*)d_in[7];  const float* bq = (const float*)d_in[8];
    const float* Wv = (const float*)d_in[9];  const float* bv = (const float*)d_in[10];
    const float* Wr = (const float*)d_in[11]; const float* br = (const float*)d_in[12];
    const float* u_bias = (const float*)d_in[13];
    const float* v_bias = (const float*)d_in[14];
    const float* Wff = (const float*)d_in[15]; const float* bff = (const float*)d_in[16];
    float* out = (float*)d_out;

    float *q_, *k_, *v_, *vT_, *ctx_, *R_, *S_, *qR_;
    cudaGetSymbolAddress((void**)&q_,   g_q);
    cudaGetSymbolAddress((void**)&k_,   g_k);
    cudaGetSymbolAddress((void**)&v_,   g_v);
    cudaGetSymbolAddress((void**)&vT_,  g_vT);
    cudaGetSymbolAddress((void**)&ctx_, g_ctx);
    cudaGetSymbolAddress((void**)&R_,   g_R);
    cudaGetSymbolAddress((void**)&S_,   g_S);
    cudaGetSymbolAddress((void**)&qR_,  g_qR);

    const int M = BB * LL;   // 3072
    const size_t SH_BIG  = (size_t)(128 + 128) * 36 * 2 * 4;  // 73728
    const size_t SH_AV   = (size_t)(128 + 64)  * 36 * 2 * 4;  // 55296

    static bool attr_done = false;
    if (!attr_done) {
        cudaFuncSetAttribute(gemm_tc<128,128,64,32>,
                             cudaFuncAttributeMaxDynamicSharedMemorySize, (int)SH_BIG);
        cudaFuncSetAttribute(gemm_tc<128,64,32,32>,
                             cudaFuncAttributeMaxDynamicSharedMemorySize, (int)SH_AV);
        attr_done = true;
    }

    // ---- 1) QKV + R projections in one launch (z: 0=q,1=k,2=v,3=R) ----
    {
        GPack P;
        P.d[0] = mkdesc(query, Wq, bq, q_, M, HH, HH, HH, HH, HH, 0,0,0,0,0,0, 1, 1);
        P.d[1] = mkdesc(key,   Wk, bk, k_, M, HH, HH, HH, HH, HH, 0,0,0,0,0,0, 1, 1);
        P.d[2] = mkdesc(value, Wv, bv, v_, M, HH, HH, HH, HH, HH, 0,0,0,0,0,0, 1, 1);
        P.d[3] = mkdesc(pe,    Wr, br, R_, RROWS, HH, HH, HH, HH, HH, 0,0,0,0,0,0, 1, 1);
        dim3 g(HH / 128, (M + 127) / 128, 4);     // (4, 24, 4)
        gemm_tc<128,128,64,32><<<g, 256, SH_BIG>>>(P);
    }

    // ---- 2) bias dots + v transpose ----
    int ndots = BB * NHH * LL + NHH * RROWS;
    dots_kernel<<<(ndots + 255) / 256, 256>>>(u_bias, v_bias);
    transpose_v<<<(BB * NHH * DHH * LL + 255) / 256, 256>>>();

    // ---- 3) A-term + Bt-term in one launch (z 0..63 = A, 64..127 = Bt) ----
    {
        GPack P;
        P.d[0] = mkdesc(q_, k_, nullptr, S_, LL, LL, DHH, HH, HH, LL,
                        (long long)LL * HH, DHH,
                        (long long)LL * HH, DHH,
                        (long long)NHH * LL * LL, (long long)LL * LL, NHH, BB * NHH);
        P.d[1] = mkdesc(q_, R_, nullptr, qR_, LL, RROWS, DHH, HH, HH, RROWS,
                        (long long)LL * HH, DHH,
                        0, DHH,
                        (long long)NHH * LL * RROWS, (long long)LL * RROWS, NHH, BB * NHH);
        P.d[2] = P.d[1]; P.d[3] = P.d[1];
        dim3 g((RROWS + 127) / 128, LL / 128, 2 * BB * NHH);   // (7, 3, 128)
        gemm_tc<128,128,64,32><<<g, 256, SH_BIG>>>(P);
    }

    // ---- 4) scores + mask + softmax ----
    softmax_kernel<<<BB * NHH * LL, 128>>>(seqlen);

    // ---- 5) AV: ctx[b,i,h,:] = attn[b,h] @ v_h ----
    {
        GPack P;
        P.d[0] = mkdesc(S_, vT_, nullptr, ctx_, LL, DHH, LL, LL, LL, HH,
                        (long long)NHH * LL * LL, (long long)LL * LL,
                        (long long)NHH * DHH * LL, (long long)DHH * LL,
                        (long long)LL * HH, DHH, NHH, BB * NHH);
        P.d[1] = P.d[0]; P.d[2] = P.d[0]; P.d[3] = P.d[0];
        dim3 g(1, LL / 128, BB * NHH);            // (1, 3, 64)
        gemm_tc<128,64,32,32><<<g, 256, SH_AV>>>(P);
    }

    // ---- 6) final FF: out = ctx @ Wff.T + bff ----
    {
        GPack P;
        P.d[0] = mkdesc(ctx_, Wff, bff, out, M, HH, HH, HH, HH, HH, 0,0,0,0,0,0, 1, 1);
        P.d[1] = P.d[0]; P.d[2] = P.d[0]; P.d[3] = P.d[0];
        dim3 g(HH / 128, (M + 127) / 128, 1);     // (4, 24)
        gemm_tc<128,128,64,32><<<g, 256, SH_BIG>>>(P);
    }
}